// round 4
// baseline (speedup 1.0000x reference)
#include <cuda_runtime.h>
#include <cuda_bf16.h>

#define D_DIM 128
#define MAX_NODES 100000

// Per-node projections: [n][0:16] = h[n]·W_s + b (P), [n][16:32] = h[n]·W_d (Q).
// 100k * 32 * 4B = 12.8 MB -> resident in L2 (126 MB).
__device__ float g_PQ[(size_t)MAX_NODES * 32];
__device__ int g_idx64;

// ---------------------------------------------------------------------------
// Kernel 1: PQ tile GEMM. Block = 128 threads = 128 nodes.
// Thread t: nodes ng*8..ng*8+7 (ng = t>>3), cols cg*4..cg*4+3 (cg = t&7).
// h read directly from global as float4 k-tiles (ng-sibling lanes share
// addresses -> in-flight dedup; each 128B line fetched once per block).
// W staged once in shared, read as broadcast LDS.128. Inner loop is pure FFMA.
// Also performs int64/int32 index detection in block 0 (ids < 100k => int64
// odd words all zero; random int32 ids give false positive ~1e-160).
// ---------------------------------------------------------------------------
__global__ __launch_bounds__(128) void precompute_kernel(const float* __restrict__ h,
                                                         const float* __restrict__ W,
                                                         const float* __restrict__ b,
                                                         const int* __restrict__ src_words,
                                                         int n_nodes) {
    __shared__ float sh_W[32][132];  // [output col][k]; 16B-aligned rows, broadcast reads

    const int t = threadIdx.x;

    if (blockIdx.x == 0 && t < 32) {
        int ok = (src_words[t * 2 + 1] == 0);
        int all = __all_sync(0xffffffffu, ok);
        if (t == 0) g_idx64 = all;
    }

    // Stage W reordered: col j<16 -> W_s row j ; j>=16 -> W_d row (j-16).
#pragma unroll
    for (int j = 0; j < 32; j++)
        sh_W[j][t] = W[(size_t)(j & 15) * 256 + ((j >> 4) << 7) + t];
    __syncthreads();

    const int n0 = blockIdx.x * 128;
    const int ng = t >> 3;
    const int cg = t & 7;
    const int c0 = cg * 4;

    // Clamped node indices (duplicate loads for OOB nodes; stores guarded).
    const float4* hrow[8];
#pragma unroll
    for (int i = 0; i < 8; i++) {
        int n = n0 + ng * 8 + i;
        if (n > n_nodes - 1) n = n_nodes - 1;
        hrow[i] = reinterpret_cast<const float4*>(h + (size_t)n * D_DIM);
    }

    float acc[8][4];
#pragma unroll
    for (int i = 0; i < 8; i++)
#pragma unroll
        for (int j = 0; j < 4; j++) acc[i][j] = 0.f;

#pragma unroll 2
    for (int kt = 0; kt < 32; kt++) {          // k-tile of 4 (one float4)
        float4 hv[8];
#pragma unroll
        for (int i = 0; i < 8; i++) hv[i] = hrow[i][kt];

        float4 wv[4];
#pragma unroll
        for (int j = 0; j < 4; j++)
            wv[j] = *reinterpret_cast<const float4*>(&sh_W[c0 + j][kt * 4]);

#pragma unroll
        for (int i = 0; i < 8; i++)
#pragma unroll
            for (int j = 0; j < 4; j++) {
                acc[i][j] = fmaf(hv[i].x, wv[j].x, acc[i][j]);
                acc[i][j] = fmaf(hv[i].y, wv[j].y, acc[i][j]);
                acc[i][j] = fmaf(hv[i].z, wv[j].z, acc[i][j]);
                acc[i][j] = fmaf(hv[i].w, wv[j].w, acc[i][j]);
            }
    }

    // Fold bias into P columns (c0 < 16), vector store.
    float4 bias = make_float4(0.f, 0.f, 0.f, 0.f);
    if (c0 < 16) bias = *reinterpret_cast<const float4*>(b + c0);

#pragma unroll
    for (int i = 0; i < 8; i++) {
        int n = n0 + ng * 8 + i;
        if (n < n_nodes)
            *reinterpret_cast<float4*>(g_PQ + (size_t)n * 32 + c0) =
                make_float4(acc[i][0] + bias.x, acc[i][1] + bias.y,
                            acc[i][2] + bias.z, acc[i][3] + bias.w);
    }
}

// ---------------------------------------------------------------------------
// Kernel 2: out[e][c] = P[src[e]][c] + Q[dst[e]][c]  (bias prefolded).
// Warp = 32 edges: coalesced idx loads (1/lane), low-32-bit shuffle
// distribution, then 4 independent gather groups (8 edges x 4 float4-lanes)
// per thread for ILP. Streaming traffic evict-first to keep PQ hot in L2.
// ---------------------------------------------------------------------------
__global__ __launch_bounds__(256) void gather_kernel(const void* __restrict__ src_raw,
                                                     const void* __restrict__ dst_raw,
                                                     float* __restrict__ out,
                                                     int n_edges) {
    const int lane = threadIdx.x & 31;
    const long long wid = (long long)blockIdx.x * (blockDim.x >> 5) + (threadIdx.x >> 5);
    const long long e0 = wid * 32;
    if (e0 >= n_edges) return;

    long long el = e0 + lane;
    long long ec = (el < n_edges) ? el : (n_edges - 1);

    int s_lo, d_lo;
    if (g_idx64) {
        s_lo = (int)__ldcs(reinterpret_cast<const long long*>(src_raw) + ec);
        d_lo = (int)__ldcs(reinterpret_cast<const long long*>(dst_raw) + ec);
    } else {
        s_lo = __ldcs(reinterpret_cast<const int*>(src_raw) + ec);
        d_lo = __ldcs(reinterpret_cast<const int*>(dst_raw) + ec);
    }

    const int sub = lane >> 2;   // edge-in-group 0..7
    const int comp = lane & 3;   // float4 within row

#pragma unroll
    for (int g = 0; g < 4; g++) {
        int esrc = g * 8 + sub;
        int se = __shfl_sync(0xffffffffu, s_lo, esrc);
        int de = __shfl_sync(0xffffffffu, d_lo, esrc);
        long long eg = e0 + esrc;
        if (eg < n_edges) {
            float4 pv = *reinterpret_cast<const float4*>(g_PQ + (size_t)se * 32 + comp * 4);
            float4 qv = *reinterpret_cast<const float4*>(g_PQ + (size_t)de * 32 + 16 + comp * 4);
            float4 r = make_float4(pv.x + qv.x, pv.y + qv.y, pv.z + qv.z, pv.w + qv.w);
            __stcs(reinterpret_cast<float4*>(out) + eg * 4 + comp, r);
        }
    }
}

// ---------------------------------------------------------------------------
// Inputs (metadata order): h [N*128 f32], src [E idx], dst [E idx],
//                          W [16*256 f32], b [16 f32]. Output: [E*16 f32].
// ---------------------------------------------------------------------------
extern "C" void kernel_launch(void* const* d_in, const int* in_sizes, int n_in,
                              void* d_out, int out_size) {
    const float* h = (const float*)d_in[0];
    const void* src = d_in[1];
    const void* dst = d_in[2];
    const float* W = (const float*)d_in[3];
    const float* b = (const float*)d_in[4];

    int n_nodes = in_sizes[0] / D_DIM;
    int n_edges = in_sizes[1];

    int blocks1 = (n_nodes + 127) / 128;
    precompute_kernel<<<blocks1, 128>>>(h, W, b, (const int*)src, n_nodes);

    // 8 warps/block, 32 edges/warp
    long long warps = ((long long)n_edges + 31) / 32;
    int blocks2 = (int)((warps + 7) / 8);
    gather_kernel<<<blocks2, 256>>>(src, dst, (float*)d_out, n_edges);
}

// round 6
// speedup vs baseline: 1.5357x; 1.5357x over previous
#include <cuda_runtime.h>
#include <cuda_bf16.h>
#include <cstdint>

#define D_DIM 128
#define MAX_NODES 100000

__device__ float g_PQ[(size_t)MAX_NODES * 32];
__device__ int g_idx64;

// Pack two floats into one bf16x2 register (low half = first arg).
__device__ __forceinline__ uint32_t packbf(float a, float b) {
    __nv_bfloat162 p = __floats2bfloat162_rn(a, b);
    return *reinterpret_cast<uint32_t*>(&p);
}

// m16n8k16 bf16 HMMA, fp32 accumulate (sm_80+; compiles on plain sm_100).
__device__ __forceinline__ void mma16816(float* c, uint32_t a0, uint32_t a1,
                                         uint32_t a2, uint32_t a3,
                                         uint32_t b0, uint32_t b1) {
    asm volatile(
        "mma.sync.aligned.m16n8k16.row.col.f32.bf16.bf16.f32 "
        "{%0,%1,%2,%3}, {%4,%5,%6,%7}, {%8,%9}, {%0,%1,%2,%3};"
        : "+f"(c[0]), "+f"(c[1]), "+f"(c[2]), "+f"(c[3])
        : "r"(a0), "r"(a1), "r"(a2), "r"(a3), "r"(b0), "r"(b1));
}

#define APAD 36   // u32 row stride: (4*g + t) mod 32 distinct -> conflict-free frags

// ---------------------------------------------------------------------------
// Kernel 1: PQ = [128-node tile] x [32 cols] x K=128 GEMM via HMMA mma.sync,
// bf16x3 split (hi*Whi + hi*Wlo + lo*Whi, fp32 accum) => fp32-grade accuracy.
// K tiled by 64 so packed-bf16 A fits in 46KB static smem.
// Warp w: rows 32w..32w+31 (2 m16 tiles) x all 32 cols (4 n8 tiles).
// Also does int64/int32 edge-index detection in block 0 (ids < 100k =>
// int64 odd words all zero; int32 random ids false-positive ~1e-160).
// ---------------------------------------------------------------------------
__global__ __launch_bounds__(128) void precompute_kernel(const float* __restrict__ h,
                                                         const float* __restrict__ W,
                                                         const float* __restrict__ b,
                                                         const int* __restrict__ src_words,
                                                         int n_nodes) {
    __shared__ uint32_t sAhi[128 * APAD];  // [row][kpair] bf16x2, k-tile of 64
    __shared__ uint32_t sAlo[128 * APAD];
    __shared__ uint32_t sWhi[32 * APAD];   // [out col][kpair] bf16x2
    __shared__ uint32_t sWlo[32 * APAD];

    const int t = threadIdx.x;
    const int warp = t >> 5;
    const int lane = t & 31;
    const int gid = lane >> 2;   // fragment group 0..7
    const int tid4 = lane & 3;   // 0..3

    if (blockIdx.x == 0 && t < 32) {
        int ok = (src_words[t * 2 + 1] == 0);
        int all = __all_sync(0xffffffffu, ok);
        if (t == 0) g_idx64 = all;
    }

    const int n0 = blockIdx.x * 128;

    float acc[2][4][4];
#pragma unroll
    for (int mt = 0; mt < 2; mt++)
#pragma unroll
        for (int nt = 0; nt < 4; nt++)
#pragma unroll
            for (int q = 0; q < 4; q++) acc[mt][nt][q] = 0.f;

    for (int kt = 0; kt < 2; kt++) {
        if (kt) __syncthreads();   // protect previous tile's reads

        // ---- stage W k-tile: out col j<16 -> W_s row j ; j>=16 -> W_d row j-16.
        {
            const int wn = t >> 2;           // out col 0..31
            const int kq = t & 3;            // 16-float chunk within the 64-k tile
            const float* wsrc = W + (size_t)(wn & 15) * 256 + ((wn >> 4) << 7)
                                  + kt * 64 + kq * 16;
            float wv[16];
#pragma unroll
            for (int i = 0; i < 4; i++)
                *reinterpret_cast<float4*>(wv + 4 * i) =
                    reinterpret_cast<const float4*>(wsrc)[i];
#pragma unroll
            for (int i = 0; i < 16; i += 2) {
                float x0 = wv[i], x1 = wv[i + 1];
                float h0 = __bfloat162float(__float2bfloat16_rn(x0));
                float h1 = __bfloat162float(__float2bfloat16_rn(x1));
                int kp = kq * 8 + i / 2;
                sWhi[wn * APAD + kp] = packbf(h0, h1);
                sWlo[wn * APAD + kp] = packbf(x0 - h0, x1 - h1);
            }
        }

        // ---- stage A k-tile: warp loads one row-chunk (256B) per step, coalesced.
#pragma unroll 8
        for (int s = 0; s < 32; s++) {
            int row = s * 4 + warp;
            int n = n0 + row;
            if (n > n_nodes - 1) n = n_nodes - 1;
            float2 v = *reinterpret_cast<const float2*>(
                h + (size_t)n * D_DIM + kt * 64 + lane * 2);
            float h0 = __bfloat162float(__float2bfloat16_rn(v.x));
            float h1 = __bfloat162float(__float2bfloat16_rn(v.y));
            sAhi[row * APAD + lane] = packbf(h0, h1);
            sAlo[row * APAD + lane] = packbf(v.x - h0, v.y - h1);
        }
        __syncthreads();

        // ---- MMA: 4 k16 steps per tile.
#pragma unroll
        for (int ks = 0; ks < 4; ks++) {
            const int kb = ks * 8 + tid4;
            uint32_t bh[4][2], bl[4][2];
#pragma unroll
            for (int nt = 0; nt < 4; nt++) {
                int base = (nt * 8 + gid) * APAD + kb;
                bh[nt][0] = sWhi[base];
                bh[nt][1] = sWhi[base + 4];
                bl[nt][0] = sWlo[base];
                bl[nt][1] = sWlo[base + 4];
            }
#pragma unroll
            for (int mt = 0; mt < 2; mt++) {
                int r0 = (warp * 32 + mt * 16 + gid) * APAD + kb;
                int r1 = r0 + 8 * APAD;
                uint32_t ah0 = sAhi[r0], ah1 = sAhi[r1];
                uint32_t ah2 = sAhi[r0 + 4], ah3 = sAhi[r1 + 4];
                uint32_t al0 = sAlo[r0], al1 = sAlo[r1];
                uint32_t al2 = sAlo[r0 + 4], al3 = sAlo[r1 + 4];
#pragma unroll
                for (int nt = 0; nt < 4; nt++) {
                    mma16816(acc[mt][nt], ah0, ah1, ah2, ah3, bh[nt][0], bh[nt][1]);
                    mma16816(acc[mt][nt], ah0, ah1, ah2, ah3, bl[nt][0], bl[nt][1]);
                    mma16816(acc[mt][nt], al0, al1, al2, al3, bh[nt][0], bh[nt][1]);
                }
            }
        }
    }

    // ---- epilogue: D[g][2t..2t+1] = c0,c1 ; D[g+8][...] = c2,c3. Bias on cols<16.
#pragma unroll
    for (int nt = 0; nt < 4; nt++) {
        int col = nt * 8 + 2 * tid4;
        float2 bias = make_float2(0.f, 0.f);
        if (nt < 2) bias = *reinterpret_cast<const float2*>(b + col);
#pragma unroll
        for (int mt = 0; mt < 2; mt++) {
            int row0 = n0 + warp * 32 + mt * 16 + gid;
            if (row0 < n_nodes)
                *reinterpret_cast<float2*>(g_PQ + (size_t)row0 * 32 + col) =
                    make_float2(acc[mt][nt][0] + bias.x, acc[mt][nt][1] + bias.y);
            if (row0 + 8 < n_nodes)
                *reinterpret_cast<float2*>(g_PQ + (size_t)(row0 + 8) * 32 + col) =
                    make_float2(acc[mt][nt][2] + bias.x, acc[mt][nt][3] + bias.y);
        }
    }
}

// ---------------------------------------------------------------------------
// Kernel 2: out[e][c] = P[src[e]][c] + Q[dst[e]][c]  (bias prefolded).
// 64 edges/warp: 2 coalesced idx loads/lane, shuffle distribution,
// 8 independent gather groups => 16 outstanding gathers per thread.
// Streaming traffic evict-first; 12.8MB PQ stays hot in L2.
// ---------------------------------------------------------------------------
__global__ __launch_bounds__(256) void gather_kernel(const void* __restrict__ src_raw,
                                                     const void* __restrict__ dst_raw,
                                                     float* __restrict__ out,
                                                     int n_edges) {
    const int lane = threadIdx.x & 31;
    const long long wid = (long long)blockIdx.x * (blockDim.x >> 5) + (threadIdx.x >> 5);
    const long long e0 = wid * 64;
    if (e0 >= n_edges) return;

    long long ea = e0 + lane, eb = e0 + 32 + lane;
    if (ea > n_edges - 1) ea = n_edges - 1;
    if (eb > n_edges - 1) eb = n_edges - 1;

    int s0, s1, d0, d1;
    if (g_idx64) {
        s0 = (int)__ldcs(reinterpret_cast<const long long*>(src_raw) + ea);
        s1 = (int)__ldcs(reinterpret_cast<const long long*>(src_raw) + eb);
        d0 = (int)__ldcs(reinterpret_cast<const long long*>(dst_raw) + ea);
        d1 = (int)__ldcs(reinterpret_cast<const long long*>(dst_raw) + eb);
    } else {
        s0 = __ldcs(reinterpret_cast<const int*>(src_raw) + ea);
        s1 = __ldcs(reinterpret_cast<const int*>(src_raw) + eb);
        d0 = __ldcs(reinterpret_cast<const int*>(dst_raw) + ea);
        d1 = __ldcs(reinterpret_cast<const int*>(dst_raw) + eb);
    }

    const int sub = lane >> 2;    // edge-in-group 0..7
    const int comp = lane & 3;    // float4 within 32-float row

#pragma unroll
    for (int g = 0; g < 8; g++) {
        int srcl = (g & 3) * 8 + sub;
        int se = __shfl_sync(0xffffffffu, (g < 4) ? s0 : s1, srcl);
        int de = __shfl_sync(0xffffffffu, (g < 4) ? d0 : d1, srcl);
        long long eg = e0 + g * 8 + sub;
        if (eg < n_edges) {
            float4 pv = *reinterpret_cast<const float4*>(g_PQ + (size_t)se * 32 + comp * 4);
            float4 qv = *reinterpret_cast<const float4*>(g_PQ + (size_t)de * 32 + 16 + comp * 4);
            float4 r = make_float4(pv.x + qv.x, pv.y + qv.y, pv.z + qv.z, pv.w + qv.w);
            __stcs(reinterpret_cast<float4*>(out) + eg * 4 + comp, r);
        }
    }
}

// ---------------------------------------------------------------------------
// Inputs (metadata order): h [N*128 f32], src [E idx], dst [E idx],
//                          W [16*256 f32], b [16 f32]. Output: [E*16 f32].
// ---------------------------------------------------------------------------
extern "C" void kernel_launch(void* const* d_in, const int* in_sizes, int n_in,
                              void* d_out, int out_size) {
    const float* h = (const float*)d_in[0];
    const void* src = d_in[1];
    const void* dst = d_in[2];
    const float* W = (const float*)d_in[3];
    const float* b = (const float*)d_in[4];

    int n_nodes = in_sizes[0] / D_DIM;
    int n_edges = in_sizes[1];

    int blocks1 = (n_nodes + 127) / 128;
    precompute_kernel<<<blocks1, 128>>>(h, W, b, (const int*)src, n_nodes);

    long long warps = ((long long)n_edges + 63) / 64;
    int blocks2 = (int)((warps + 7) / 8);
    gather_kernel<<<blocks2, 256>>>(src, dst, (float*)d_out, n_edges);
}

// round 7
// speedup vs baseline: 1.7363x; 1.1306x over previous
#include <cuda_runtime.h>
#include <cuda_bf16.h>
#include <cstdint>

#define D_DIM 128
#define MAX_NODES 100000

__device__ float g_PQ[(size_t)MAX_NODES * 32];
__device__ int g_idx64;

// Pack two floats into one bf16x2 register (low half = first arg).
__device__ __forceinline__ uint32_t packbf(float a, float b) {
    __nv_bfloat162 p = __floats2bfloat162_rn(a, b);
    return *reinterpret_cast<uint32_t*>(&p);
}

// m16n8k16 bf16 HMMA, fp32 accumulate (sm_80+; compiles on plain sm_100).
__device__ __forceinline__ void mma16816(float* c, uint32_t a0, uint32_t a1,
                                         uint32_t a2, uint32_t a3,
                                         uint32_t b0, uint32_t b1) {
    asm volatile(
        "mma.sync.aligned.m16n8k16.row.col.f32.bf16.bf16.f32 "
        "{%0,%1,%2,%3}, {%4,%5,%6,%7}, {%8,%9}, {%0,%1,%2,%3};"
        : "+f"(c[0]), "+f"(c[1]), "+f"(c[2]), "+f"(c[3])
        : "r"(a0), "r"(a1), "r"(a2), "r"(a3), "r"(b0), "r"(b1));
}

#define APAD 36   // kpairs/row for A k-tile (32+4): gid*36+tid4 mod 32 distinct
#define WPAD 68   // kpairs/row for W full-K (64+4): gid*68+tid4 mod 32 distinct

// smem layout (u32 units): sAhi[128*36]=0, sAlo=4608, sWhi[32*68]=9216, sWlo=11392
#define SM_ALO 4608
#define SM_WHI 9216
#define SM_WLO 11392
#define SMEM_BYTES (13568 * 4)

// ---------------------------------------------------------------------------
// Kernel 1: PQ = [128-node tile] x [32 cols] x K=128 GEMM via HMMA mma.sync,
// bf16x3 split (hi*Whi + hi*Wlo + lo*Whi, fp32 accum) => ~1e-6 rel err.
// 256 threads; warp w owns rows 16w..16w+15 x all 32 cols. K tiled by 64;
// k-tile-1 A is PREFETCHED into registers during k-tile-0 MMA.
// Block 0 also detects int64 vs int32 edge indices (ids < 100k => int64
// odd words all zero; int32 random ids false-positive ~1e-160).
// ---------------------------------------------------------------------------
__global__ __launch_bounds__(256) void precompute_kernel(const float* __restrict__ h,
                                                         const float* __restrict__ W,
                                                         const float* __restrict__ b,
                                                         const int* __restrict__ src_words,
                                                         int n_nodes) {
    extern __shared__ uint32_t smem[];
    uint32_t* sAhi = smem;
    uint32_t* sAlo = smem + SM_ALO;
    uint32_t* sWhi = smem + SM_WHI;
    uint32_t* sWlo = smem + SM_WLO;

    const int t = threadIdx.x;
    const int warp = t >> 5;
    const int lane = t & 31;
    const int gid = lane >> 2;   // fragment group 0..7
    const int tid4 = lane & 3;   // 0..3

    if (blockIdx.x == 0 && t < 32) {
        int ok = (src_words[t * 2 + 1] == 0);
        int all = __all_sync(0xffffffffu, ok);
        if (t == 0) g_idx64 = all;
    }

    const int n0 = blockIdx.x * 128;

    // ---- stage W for full K=128: out col j<16 -> W_s row j ; j>=16 -> W_d row j-16.
#pragma unroll
    for (int s = 0; s < 4; s++) {
        int idx = s * 256 + t;
        int col = idx >> 5;       // 0..31
        int f4 = idx & 31;        // float4 within 128 k-values
        float4 wv = *reinterpret_cast<const float4*>(
            W + (size_t)(col & 15) * 256 + ((col >> 4) << 7) + f4 * 4);
        float h0 = __bfloat162float(__float2bfloat16_rn(wv.x));
        float h1 = __bfloat162float(__float2bfloat16_rn(wv.y));
        float h2 = __bfloat162float(__float2bfloat16_rn(wv.z));
        float h3 = __bfloat162float(__float2bfloat16_rn(wv.w));
        uint2 hi = make_uint2(packbf(h0, h1), packbf(h2, h3));
        uint2 lo = make_uint2(packbf(wv.x - h0, wv.y - h1), packbf(wv.z - h2, wv.w - h3));
        *reinterpret_cast<uint2*>(&sWhi[col * WPAD + f4 * 2]) = hi;
        *reinterpret_cast<uint2*>(&sWlo[col * WPAD + f4 * 2]) = lo;
    }

    // ---- stage A k-tile 0 (k 0..63)
#pragma unroll
    for (int s = 0; s < 8; s++) {
        int idx = s * 256 + t;
        int row = idx >> 4;       // 0..127
        int f4 = idx & 15;        // float4 within 64 k-values
        int n = n0 + row;
        if (n > n_nodes - 1) n = n_nodes - 1;
        float4 v = *reinterpret_cast<const float4*>(h + (size_t)n * D_DIM + f4 * 4);
        float h0 = __bfloat162float(__float2bfloat16_rn(v.x));
        float h1 = __bfloat162float(__float2bfloat16_rn(v.y));
        float h2 = __bfloat162float(__float2bfloat16_rn(v.z));
        float h3 = __bfloat162float(__float2bfloat16_rn(v.w));
        *reinterpret_cast<uint2*>(&sAhi[row * APAD + f4 * 2]) =
            make_uint2(packbf(h0, h1), packbf(h2, h3));
        *reinterpret_cast<uint2*>(&sAlo[row * APAD + f4 * 2]) =
            make_uint2(packbf(v.x - h0, v.y - h1), packbf(v.z - h2, v.w - h3));
    }
    __syncthreads();

    // ---- prefetch k-tile 1 A (k 64..127) into registers (overlaps kt0 MMA)
    float4 pf[8];
#pragma unroll
    for (int s = 0; s < 8; s++) {
        int idx = s * 256 + t;
        int row = idx >> 4;
        int f4 = idx & 15;
        int n = n0 + row;
        if (n > n_nodes - 1) n = n_nodes - 1;
        pf[s] = *reinterpret_cast<const float4*>(h + (size_t)n * D_DIM + 64 + f4 * 4);
    }

    float acc[4][4];
#pragma unroll
    for (int nt = 0; nt < 4; nt++)
#pragma unroll
        for (int q = 0; q < 4; q++) acc[nt][q] = 0.f;

    // ---- MMA k-tile 0
#pragma unroll
    for (int ks = 0; ks < 4; ks++) {
        const int kb = ks * 8 + tid4;
        int r0 = (warp * 16 + gid) * APAD + kb;
        int r1 = r0 + 8 * APAD;
        uint32_t ah0 = sAhi[r0], ah1 = sAhi[r1], ah2 = sAhi[r0 + 4], ah3 = sAhi[r1 + 4];
        uint32_t al0 = sAlo[r0], al1 = sAlo[r1], al2 = sAlo[r0 + 4], al3 = sAlo[r1 + 4];
#pragma unroll
        for (int nt = 0; nt < 4; nt++) {
            int base = (nt * 8 + gid) * WPAD + kb;   // kt0: kpairs 0..31
            uint32_t b0 = sWhi[base], b1 = sWhi[base + 4];
            uint32_t l0 = sWlo[base], l1 = sWlo[base + 4];
            mma16816(acc[nt], ah0, ah1, ah2, ah3, b0, b1);
            mma16816(acc[nt], ah0, ah1, ah2, ah3, l0, l1);
            mma16816(acc[nt], al0, al1, al2, al3, b0, b1);
        }
    }
    __syncthreads();

    // ---- store prefetched k-tile 1 A
#pragma unroll
    for (int s = 0; s < 8; s++) {
        int idx = s * 256 + t;
        int row = idx >> 4;
        int f4 = idx & 15;
        float4 v = pf[s];
        float h0 = __bfloat162float(__float2bfloat16_rn(v.x));
        float h1 = __bfloat162float(__float2bfloat16_rn(v.y));
        float h2 = __bfloat162float(__float2bfloat16_rn(v.z));
        float h3 = __bfloat162float(__float2bfloat16_rn(v.w));
        *reinterpret_cast<uint2*>(&sAhi[row * APAD + f4 * 2]) =
            make_uint2(packbf(h0, h1), packbf(h2, h3));
        *reinterpret_cast<uint2*>(&sAlo[row * APAD + f4 * 2]) =
            make_uint2(packbf(v.x - h0, v.y - h1), packbf(v.z - h2, v.w - h3));
    }
    __syncthreads();

    // ---- MMA k-tile 1 (W kpairs 32..63)
#pragma unroll
    for (int ks = 0; ks < 4; ks++) {
        const int kb = ks * 8 + tid4;
        int r0 = (warp * 16 + gid) * APAD + kb;
        int r1 = r0 + 8 * APAD;
        uint32_t ah0 = sAhi[r0], ah1 = sAhi[r1], ah2 = sAhi[r0 + 4], ah3 = sAhi[r1 + 4];
        uint32_t al0 = sAlo[r0], al1 = sAlo[r1], al2 = sAlo[r0 + 4], al3 = sAlo[r1 + 4];
#pragma unroll
        for (int nt = 0; nt < 4; nt++) {
            int base = (nt * 8 + gid) * WPAD + 32 + kb;
            uint32_t b0 = sWhi[base], b1 = sWhi[base + 4];
            uint32_t l0 = sWlo[base], l1 = sWlo[base + 4];
            mma16816(acc[nt], ah0, ah1, ah2, ah3, b0, b1);
            mma16816(acc[nt], ah0, ah1, ah2, ah3, l0, l1);
            mma16816(acc[nt], al0, al1, al2, al3, b0, b1);
        }
    }

    // ---- epilogue: c0,c1 -> row gid, c2,c3 -> row gid+8; bias on cols<16.
#pragma unroll
    for (int nt = 0; nt < 4; nt++) {
        int col = nt * 8 + 2 * tid4;
        float2 bias = make_float2(0.f, 0.f);
        if (nt < 2) bias = *reinterpret_cast<const float2*>(b + col);
        int row0 = n0 + warp * 16 + gid;
        if (row0 < n_nodes)
            *reinterpret_cast<float2*>(g_PQ + (size_t)row0 * 32 + col) =
                make_float2(acc[nt][0] + bias.x, acc[nt][1] + bias.y);
        if (row0 + 8 < n_nodes)
            *reinterpret_cast<float2*>(g_PQ + (size_t)(row0 + 8) * 32 + col) =
                make_float2(acc[nt][2] + bias.x, acc[nt][3] + bias.y);
    }
}

// ---------------------------------------------------------------------------
// Kernel 2: out[e][c] = P[src[e]][c] + Q[dst[e]][c]  (bias prefolded).
// 64 edges/warp: 2 coalesced idx loads/lane, shuffle distribution,
// 8 gather groups => 16 outstanding gathers/thread. PQ loads via __ldcg
// (L2-only; no L1 allocation — data can't hit L1 anyway). Streams evict-first.
// ---------------------------------------------------------------------------
__global__ __launch_bounds__(256) void gather_kernel(const void* __restrict__ src_raw,
                                                     const void* __restrict__ dst_raw,
                                                     float* __restrict__ out,
                                                     int n_edges) {
    const int lane = threadIdx.x & 31;
    const long long wid = (long long)blockIdx.x * (blockDim.x >> 5) + (threadIdx.x >> 5);
    const long long e0 = wid * 64;
    if (e0 >= n_edges) return;

    long long ea = e0 + lane, eb = e0 + 32 + lane;
    if (ea > n_edges - 1) ea = n_edges - 1;
    if (eb > n_edges - 1) eb = n_edges - 1;

    int s0, s1, d0, d1;
    if (g_idx64) {
        s0 = (int)__ldcs(reinterpret_cast<const long long*>(src_raw) + ea);
        s1 = (int)__ldcs(reinterpret_cast<const long long*>(src_raw) + eb);
        d0 = (int)__ldcs(reinterpret_cast<const long long*>(dst_raw) + ea);
        d1 = (int)__ldcs(reinterpret_cast<const long long*>(dst_raw) + eb);
    } else {
        s0 = __ldcs(reinterpret_cast<const int*>(src_raw) + ea);
        s1 = __ldcs(reinterpret_cast<const int*>(src_raw) + eb);
        d0 = __ldcs(reinterpret_cast<const int*>(dst_raw) + ea);
        d1 = __ldcs(reinterpret_cast<const int*>(dst_raw) + eb);
    }

    const int sub = lane >> 2;    // edge-in-group 0..7
    const int comp = lane & 3;    // float4 within 32-float row

#pragma unroll
    for (int g = 0; g < 8; g++) {
        int srcl = (g & 3) * 8 + sub;
        int se = __shfl_sync(0xffffffffu, (g < 4) ? s0 : s1, srcl);
        int de = __shfl_sync(0xffffffffu, (g < 4) ? d0 : d1, srcl);
        long long eg = e0 + g * 8 + sub;
        if (eg < n_edges) {
            float4 pv = __ldcg(reinterpret_cast<const float4*>(
                g_PQ + (size_t)se * 32 + comp * 4));
            float4 qv = __ldcg(reinterpret_cast<const float4*>(
                g_PQ + (size_t)de * 32 + 16 + comp * 4));
            float4 r = make_float4(pv.x + qv.x, pv.y + qv.y, pv.z + qv.z, pv.w + qv.w);
            __stcs(reinterpret_cast<float4*>(out) + eg * 4 + comp, r);
        }
    }
}

// ---------------------------------------------------------------------------
// Inputs (metadata order): h [N*128 f32], src [E idx], dst [E idx],
//                          W [16*256 f32], b [16 f32]. Output: [E*16 f32].
// ---------------------------------------------------------------------------
extern "C" void kernel_launch(void* const* d_in, const int* in_sizes, int n_in,
                              void* d_out, int out_size) {
    const float* h = (const float*)d_in[0];
    const void* src = d_in[1];
    const void* dst = d_in[2];
    const float* W = (const float*)d_in[3];
    const float* b = (const float*)d_in[4];

    int n_nodes = in_sizes[0] / D_DIM;
    int n_edges = in_sizes[1];

    cudaFuncSetAttribute(precompute_kernel,
                         cudaFuncAttributeMaxDynamicSharedMemorySize, SMEM_BYTES);

    int blocks1 = (n_nodes + 127) / 128;
    precompute_kernel<<<blocks1, 256, SMEM_BYTES>>>(h, W, b, (const int*)src, n_nodes);

    long long warps = ((long long)n_edges + 63) / 64;
    int blocks2 = (int)((warps + 7) / 8);
    gather_kernel<<<blocks2, 256>>>(src, dst, (float*)d_out, n_edges);
}

// round 8
// speedup vs baseline: 1.7905x; 1.0312x over previous
#include <cuda_runtime.h>
#include <cuda_bf16.h>
#include <cstdint>

#define D_DIM 128
#define MAX_NODES 100000

__device__ float g_PQ[(size_t)MAX_NODES * 32];
__device__ int g_idx64;

// Pack two floats into one bf16x2 register (low half = first arg).
__device__ __forceinline__ uint32_t packbf(float a, float b) {
    __nv_bfloat162 p = __floats2bfloat162_rn(a, b);
    return *reinterpret_cast<uint32_t*>(&p);
}

// m16n8k16 bf16 HMMA, fp32 accumulate (sm_80+; compiles on plain sm_100).
__device__ __forceinline__ void mma16816(float* c, uint32_t a0, uint32_t a1,
                                         uint32_t a2, uint32_t a3,
                                         uint32_t b0, uint32_t b1) {
    asm volatile(
        "mma.sync.aligned.m16n8k16.row.col.f32.bf16.bf16.f32 "
        "{%0,%1,%2,%3}, {%4,%5,%6,%7}, {%8,%9}, {%0,%1,%2,%3};"
        : "+f"(c[0]), "+f"(c[1]), "+f"(c[2]), "+f"(c[3])
        : "r"(a0), "r"(a1), "r"(a2), "r"(a3), "r"(b0), "r"(b1));
}

#define APAD 36   // kpairs/row for A k-tile (32+4): gid*36+tid4 mod 32 distinct
#define WPAD 68   // kpairs/row for W full-K (64+4): gid*68+tid4 mod 32 distinct

// smem layout (u32 units): sAhi[128*36]=0, sAlo=4608, sWhi[32*68]=9216, sWlo=11392
#define SM_ALO 4608
#define SM_WHI 9216
#define SM_WLO 11392
#define SMEM_BYTES (13568 * 4)

// ---------------------------------------------------------------------------
// Kernel 1: PQ = [128-node tile] x [32 cols] x K=128 GEMM via HMMA mma.sync,
// bf16x3 split (hi*Whi + hi*Wlo + lo*Whi, fp32 accum) => ~1e-6 rel err.
// 256 threads; warp w owns rows 16w..16w+15 x all 32 cols. K tiled by 64;
// k-tile-1 A is PREFETCHED into registers during k-tile-0 MMA.
// Block 0 also detects int64 vs int32 edge indices (ids < 100k => int64
// odd words all zero; int32 random ids false-positive ~1e-160).
// ---------------------------------------------------------------------------
__global__ __launch_bounds__(256) void precompute_kernel(const float* __restrict__ h,
                                                         const float* __restrict__ W,
                                                         const float* __restrict__ b,
                                                         const int* __restrict__ src_words,
                                                         int n_nodes) {
    extern __shared__ uint32_t smem[];
    uint32_t* sAhi = smem;
    uint32_t* sAlo = smem + SM_ALO;
    uint32_t* sWhi = smem + SM_WHI;
    uint32_t* sWlo = smem + SM_WLO;

    const int t = threadIdx.x;
    const int warp = t >> 5;
    const int lane = t & 31;
    const int gid = lane >> 2;   // fragment group 0..7
    const int tid4 = lane & 3;   // 0..3

    if (blockIdx.x == 0 && t < 32) {
        int ok = (src_words[t * 2 + 1] == 0);
        int all = __all_sync(0xffffffffu, ok);
        if (t == 0) g_idx64 = all;
    }

    const int n0 = blockIdx.x * 128;

    // ---- stage W for full K=128: out col j<16 -> W_s row j ; j>=16 -> W_d row j-16.
#pragma unroll
    for (int s = 0; s < 4; s++) {
        int idx = s * 256 + t;
        int col = idx >> 5;       // 0..31
        int f4 = idx & 31;        // float4 within 128 k-values
        float4 wv = *reinterpret_cast<const float4*>(
            W + (size_t)(col & 15) * 256 + ((col >> 4) << 7) + f4 * 4);
        float h0 = __bfloat162float(__float2bfloat16_rn(wv.x));
        float h1 = __bfloat162float(__float2bfloat16_rn(wv.y));
        float h2 = __bfloat162float(__float2bfloat16_rn(wv.z));
        float h3 = __bfloat162float(__float2bfloat16_rn(wv.w));
        uint2 hi = make_uint2(packbf(h0, h1), packbf(h2, h3));
        uint2 lo = make_uint2(packbf(wv.x - h0, wv.y - h1), packbf(wv.z - h2, wv.w - h3));
        *reinterpret_cast<uint2*>(&sWhi[col * WPAD + f4 * 2]) = hi;
        *reinterpret_cast<uint2*>(&sWlo[col * WPAD + f4 * 2]) = lo;
    }

    // ---- stage A k-tile 0 (k 0..63)
#pragma unroll
    for (int s = 0; s < 8; s++) {
        int idx = s * 256 + t;
        int row = idx >> 4;       // 0..127
        int f4 = idx & 15;        // float4 within 64 k-values
        int n = n0 + row;
        if (n > n_nodes - 1) n = n_nodes - 1;
        float4 v = *reinterpret_cast<const float4*>(h + (size_t)n * D_DIM + f4 * 4);
        float h0 = __bfloat162float(__float2bfloat16_rn(v.x));
        float h1 = __bfloat162float(__float2bfloat16_rn(v.y));
        float h2 = __bfloat162float(__float2bfloat16_rn(v.z));
        float h3 = __bfloat162float(__float2bfloat16_rn(v.w));
        *reinterpret_cast<uint2*>(&sAhi[row * APAD + f4 * 2]) =
            make_uint2(packbf(h0, h1), packbf(h2, h3));
        *reinterpret_cast<uint2*>(&sAlo[row * APAD + f4 * 2]) =
            make_uint2(packbf(v.x - h0, v.y - h1), packbf(v.z - h2, v.w - h3));
    }
    __syncthreads();

    // ---- prefetch k-tile 1 A (k 64..127) into registers (overlaps kt0 MMA)
    float4 pf[8];
#pragma unroll
    for (int s = 0; s < 8; s++) {
        int idx = s * 256 + t;
        int row = idx >> 4;
        int f4 = idx & 15;
        int n = n0 + row;
        if (n > n_nodes - 1) n = n_nodes - 1;
        pf[s] = *reinterpret_cast<const float4*>(h + (size_t)n * D_DIM + 64 + f4 * 4);
    }

    float acc[4][4];
#pragma unroll
    for (int nt = 0; nt < 4; nt++)
#pragma unroll
        for (int q = 0; q < 4; q++) acc[nt][q] = 0.f;

    // ---- MMA k-tile 0
#pragma unroll
    for (int ks = 0; ks < 4; ks++) {
        const int kb = ks * 8 + tid4;
        int r0 = (warp * 16 + gid) * APAD + kb;
        int r1 = r0 + 8 * APAD;
        uint32_t ah0 = sAhi[r0], ah1 = sAhi[r1], ah2 = sAhi[r0 + 4], ah3 = sAhi[r1 + 4];
        uint32_t al0 = sAlo[r0], al1 = sAlo[r1], al2 = sAlo[r0 + 4], al3 = sAlo[r1 + 4];
#pragma unroll
        for (int nt = 0; nt < 4; nt++) {
            int base = (nt * 8 + gid) * WPAD + kb;   // kt0: kpairs 0..31
            uint32_t b0 = sWhi[base], b1 = sWhi[base + 4];
            uint32_t l0 = sWlo[base], l1 = sWlo[base + 4];
            mma16816(acc[nt], ah0, ah1, ah2, ah3, b0, b1);
            mma16816(acc[nt], ah0, ah1, ah2, ah3, l0, l1);
            mma16816(acc[nt], al0, al1, al2, al3, b0, b1);
        }
    }
    __syncthreads();

    // ---- store prefetched k-tile 1 A
#pragma unroll
    for (int s = 0; s < 8; s++) {
        int idx = s * 256 + t;
        int row = idx >> 4;
        int f4 = idx & 15;
        float4 v = pf[s];
        float h0 = __bfloat162float(__float2bfloat16_rn(v.x));
        float h1 = __bfloat162float(__float2bfloat16_rn(v.y));
        float h2 = __bfloat162float(__float2bfloat16_rn(v.z));
        float h3 = __bfloat162float(__float2bfloat16_rn(v.w));
        *reinterpret_cast<uint2*>(&sAhi[row * APAD + f4 * 2]) =
            make_uint2(packbf(h0, h1), packbf(h2, h3));
        *reinterpret_cast<uint2*>(&sAlo[row * APAD + f4 * 2]) =
            make_uint2(packbf(v.x - h0, v.y - h1), packbf(v.z - h2, v.w - h3));
    }
    __syncthreads();

    // ---- MMA k-tile 1 (W kpairs 32..63)
#pragma unroll
    for (int ks = 0; ks < 4; ks++) {
        const int kb = ks * 8 + tid4;
        int r0 = (warp * 16 + gid) * APAD + kb;
        int r1 = r0 + 8 * APAD;
        uint32_t ah0 = sAhi[r0], ah1 = sAhi[r1], ah2 = sAhi[r0 + 4], ah3 = sAhi[r1 + 4];
        uint32_t al0 = sAlo[r0], al1 = sAlo[r1], al2 = sAlo[r0 + 4], al3 = sAlo[r1 + 4];
#pragma unroll
        for (int nt = 0; nt < 4; nt++) {
            int base = (nt * 8 + gid) * WPAD + 32 + kb;
            uint32_t b0 = sWhi[base], b1 = sWhi[base + 4];
            uint32_t l0 = sWlo[base], l1 = sWlo[base + 4];
            mma16816(acc[nt], ah0, ah1, ah2, ah3, b0, b1);
            mma16816(acc[nt], ah0, ah1, ah2, ah3, l0, l1);
            mma16816(acc[nt], al0, al1, al2, al3, b0, b1);
        }
    }

    // ---- epilogue: c0,c1 -> row gid, c2,c3 -> row gid+8; bias on cols<16.
#pragma unroll
    for (int nt = 0; nt < 4; nt++) {
        int col = nt * 8 + 2 * tid4;
        float2 bias = make_float2(0.f, 0.f);
        if (nt < 2) bias = *reinterpret_cast<const float2*>(b + col);
        int row0 = n0 + warp * 16 + gid;
        if (row0 < n_nodes)
            *reinterpret_cast<float2*>(g_PQ + (size_t)row0 * 32 + col) =
                make_float2(acc[nt][0] + bias.x, acc[nt][1] + bias.y);
        if (row0 + 8 < n_nodes)
            *reinterpret_cast<float2*>(g_PQ + (size_t)(row0 + 8) * 32 + col) =
                make_float2(acc[nt][2] + bias.x, acc[nt][3] + bias.y);
    }
}

// ---------------------------------------------------------------------------
// Kernel 2: out[e][c] = P[src[e]][c] + Q[dst[e]][c]  (bias prefolded).
// 64 edges/warp, SOFTWARE-PIPELINED: per 4-group batch, all 8 gather loads
// issue back-to-back (clamped indices, no control flow) BEFORE any dependent
// add/store, giving ~8 loads in flight per thread. Stores guarded only.
// ---------------------------------------------------------------------------
__global__ __launch_bounds__(256) void gather_kernel(const void* __restrict__ src_raw,
                                                     const void* __restrict__ dst_raw,
                                                     float* __restrict__ out,
                                                     int n_edges) {
    const int lane = threadIdx.x & 31;
    const long long wid = (long long)blockIdx.x * (blockDim.x >> 5) + (threadIdx.x >> 5);
    const long long e0 = wid * 64;
    if (e0 >= n_edges) return;

    long long ea = e0 + lane, eb = e0 + 32 + lane;
    if (ea > n_edges - 1) ea = n_edges - 1;
    if (eb > n_edges - 1) eb = n_edges - 1;

    int s0, s1, d0, d1;
    if (g_idx64) {
        s0 = (int)__ldcs(reinterpret_cast<const long long*>(src_raw) + ea);
        s1 = (int)__ldcs(reinterpret_cast<const long long*>(src_raw) + eb);
        d0 = (int)__ldcs(reinterpret_cast<const long long*>(dst_raw) + ea);
        d1 = (int)__ldcs(reinterpret_cast<const long long*>(dst_raw) + eb);
    } else {
        s0 = __ldcs(reinterpret_cast<const int*>(src_raw) + ea);
        s1 = __ldcs(reinterpret_cast<const int*>(src_raw) + eb);
        d0 = __ldcs(reinterpret_cast<const int*>(dst_raw) + ea);
        d1 = __ldcs(reinterpret_cast<const int*>(dst_raw) + eb);
    }

    const int sub = lane >> 2;    // edge-in-group 0..7
    const int comp = lane & 3;    // float4 within 32-float row

#pragma unroll
    for (int half = 0; half < 2; half++) {
        const int sv = half ? s1 : s0;
        const int dv = half ? d1 : d0;
        const long long ebase = e0 + half * 32 + sub;

        // Phase 1: issue all 8 gather loads (clamped idx -> always safe).
        float4 pv[4], qv[4];
#pragma unroll
        for (int g = 0; g < 4; g++) {
            int se = __shfl_sync(0xffffffffu, sv, g * 8 + sub);
            int de = __shfl_sync(0xffffffffu, dv, g * 8 + sub);
            pv[g] = __ldcg(reinterpret_cast<const float4*>(
                g_PQ + (size_t)se * 32 + comp * 4));
            qv[g] = __ldcg(reinterpret_cast<const float4*>(
                g_PQ + (size_t)de * 32 + 16 + comp * 4));
        }

        // Phase 2: guarded add + store.
#pragma unroll
        for (int g = 0; g < 4; g++) {
            long long eg = ebase + g * 8;
            if (eg < n_edges) {
                float4 r = make_float4(pv[g].x + qv[g].x, pv[g].y + qv[g].y,
                                       pv[g].z + qv[g].z, pv[g].w + qv[g].w);
                __stcs(reinterpret_cast<float4*>(out) + eg * 4 + comp, r);
            }
        }
    }
}

// ---------------------------------------------------------------------------
// Inputs (metadata order): h [N*128 f32], src [E idx], dst [E idx],
//                          W [16*256 f32], b [16 f32]. Output: [E*16 f32].
// ---------------------------------------------------------------------------
extern "C" void kernel_launch(void* const* d_in, const int* in_sizes, int n_in,
                              void* d_out, int out_size) {
    const float* h = (const float*)d_in[0];
    const void* src = d_in[1];
    const void* dst = d_in[2];
    const float* W = (const float*)d_in[3];
    const float* b = (const float*)d_in[4];

    int n_nodes = in_sizes[0] / D_DIM;
    int n_edges = in_sizes[1];

    cudaFuncSetAttribute(precompute_kernel,
                         cudaFuncAttributeMaxDynamicSharedMemorySize, SMEM_BYTES);

    int blocks1 = (n_nodes + 127) / 128;
    precompute_kernel<<<blocks1, 256, SMEM_BYTES>>>(h, W, b, (const int*)src, n_nodes);

    long long warps = ((long long)n_edges + 63) / 64;
    int blocks2 = (int)((warps + 7) / 8);
    gather_kernel<<<blocks2, 256>>>(src, dst, (float*)d_out, n_edges);
}